// round 5
// baseline (speedup 1.0000x reference)
#include <cuda_runtime.h>
#include <cstdint>

#define D      16384
#define BATCH  8
#define H0     4096

#define TK      256
#define TJ      256
#define SK      32
#define NSUB    8
#define THREADS 256

// smem layout (bytes)
#define OFF_W0  0
#define OFF_W1  32768
#define OFF_R0  65536
#define OFF_R1  66560
#define OFF_TS  67584
#define SMEM_TOTAL (OFF_TS + 16384)   // 83968 B
// F-flush overlays [0 .. 65792) after the main loop (W/rho stages dead then)

typedef unsigned long long ull;

__device__ float g_acc[BATCH * D];
__device__ ull   g_rho_bp[(size_t)D * 4];       // [k][bp]: (rho_{2bp}(k), rho_{2bp+1}(k))
__device__ ull   g_rhoc[(size_t)(D / 2) * 8];   // [j2][b]: (rho_b(2j2), rho_b(2j2+1))

__device__ __forceinline__ ull ffma2(ull a, ull b, ull c) {
    ull d;
    asm("fma.rn.f32x2 %0, %1, %2, %3;" : "=l"(d) : "l"(a), "l"(b), "l"(c));
    return d;
}
__device__ __forceinline__ ull add2(ull a, ull b) {
    ull d;
    asm("add.rn.f32x2 %0, %1, %2;" : "=l"(d) : "l"(a), "l"(b));
    return d;
}
__device__ __forceinline__ float sigmoid4(float x) {
    return 1.0f / (1.0f + expf(-4.0f * (x - 0.5f)));
}
__device__ __forceinline__ void cpa16(void* smem_dst, const void* gmem_src) {
    uint32_t sa = (uint32_t)__cvta_generic_to_shared(smem_dst);
    asm volatile("cp.async.cg.shared.global [%0], [%1], 16;\n" :: "r"(sa), "l"(gmem_src));
}
__device__ __forceinline__ ull packf2(float x, float y) {
    float2 v = make_float2(x, y);
    return *reinterpret_cast<ull*>(&v);
}

// ---------------------------------------------------------------------------
// Kernel 1: zero acc + build compact rho tables (coalesced writes)
// grid 512 x 256 = 131072 threads
// ---------------------------------------------------------------------------
__global__ void prep_kernel(const float* __restrict__ s) {
    int idx = blockIdx.x * blockDim.x + threadIdx.x;
    g_acc[idx] = 0.0f;
    if (idx < D * 4) {          // b-pair table for F
        int k = idx >> 2, i = idx & 3;
        g_rho_bp[idx] = packf2(sigmoid4(s[(2 * i) * D + k]),
                               sigmoid4(s[(2 * i + 1) * D + k]));
    }
    if (idx < (D / 2) * 8) {    // j-pair table for T
        int j2 = idx >> 3, b = idx & 7;
        g_rhoc[idx] = packf2(sigmoid4(s[b * D + 2 * j2]),
                             sigmoid4(s[b * D + 2 * j2 + 1]));
    }
}

// ---------------------------------------------------------------------------
// Kernel 2: symmetric block-tridiag matmul; each 256x256 upper-block tile is
// read from DRAM once and used in BOTH directions (F: rho_R @ B, T: rho_C @ B^T)
// in a single fused inner loop. rhoc lives in registers; rho b-pairs broadcast.
// ---------------------------------------------------------------------------
__global__ __launch_bounds__(THREADS, 1)
void mm_kernel(const float* __restrict__ W) {
    extern __shared__ char smem[];
    const int t    = threadIdx.x;
    const int lane = t & 31;
    const int w    = t >> 5;        // warp 0..7 = k-row group
    const int jc   = lane;          // col chunk (8 cols each)

    const int cta  = blockIdx.x;    // 0..767
    const int b3   = cta >> 8;
    const int rem  = cta & 255;
    const int it   = rem >> 4;
    const int jt   = rem & 15;
    const int row0 = b3 * 4096 + it * TK;
    const int col0 = (b3 + 1) * 4096 + jt * TJ;

    // rhoc for this thread's 8 fixed cols: 4 j-pairs x 8 batches, in registers
    ull rc[32];
    {
        const int j2b = (col0 >> 1) + jc * 4;
#pragma unroll
        for (int cp = 0; cp < 4; cp++)
#pragma unroll
            for (int b = 0; b < 8; b++)
                rc[cp * 8 + b] = g_rhoc[(size_t)(j2b + cp) * 8 + b];
    }

    auto load_sub = [&](int s, int stg) {
        char* dst = smem + (stg ? OFF_W1 : OFF_W0);
        const float* src = W + (size_t)(row0 + s * SK) * D + col0;
#pragma unroll
        for (int i = 0; i < 8; i++) {
            int idx = t + THREADS * i;          // 0..2047
            int r  = idx >> 6;
            int c4 = idx & 63;
            cpa16(dst + r * 1024 + c4 * 16, src + (size_t)r * D + c4 * 4);
        }
        if (t < 64) {
            char* rdst = smem + (stg ? OFF_R1 : OFF_R0);
            const char* rsrc = (const char*)g_rho_bp + (size_t)(row0 + s * SK) * 32;
            cpa16(rdst + t * 16, rsrc + t * 16);
        }
    };

    ull accF[32];
#pragma unroll
    for (int i = 0; i < 32; i++) accF[i] = 0ull;

    load_sub(0, 0);
    asm volatile("cp.async.commit_group;\n");

    int stg = 0;
    for (int s = 0; s < NSUB; s++) {
        if (s + 1 < NSUB) {
            load_sub(s + 1, stg ^ 1);
            asm volatile("cp.async.commit_group;\n");
            asm volatile("cp.async.wait_group 1;\n");
        } else {
            asm volatile("cp.async.wait_group 0;\n");
        }
        __syncthreads();

        const char* wbuf = smem + (stg ? OFF_W1 : OFF_W0);
        const char* rbuf = smem + (stg ? OFF_R1 : OFF_R0);
        ull* sT = (ull*)(smem + OFF_TS);

#pragma unroll
        for (int kq = 0; kq < 4; kq++) {
            const int row = w * 4 + kq;

            ull w8[4];
            {
                const ulonglong2* p = (const ulonglong2*)(wbuf + row * 1024 + jc * 32);
                ulonglong2 a = p[0], b_ = p[1];
                w8[0] = a.x; w8[1] = a.y; w8[2] = b_.x; w8[3] = b_.y;
            }
            ull dup[8];
            {
                const ulonglong2* p = (const ulonglong2*)(rbuf + row * 32);
                ulonglong2 a = p[0], b_ = p[1];
                ull bp[4] = {a.x, a.y, b_.x, b_.y};
#pragma unroll
                for (int i = 0; i < 4; i++) {
                    float2 v = *reinterpret_cast<float2*>(&bp[i]);
                    dup[2 * i]     = packf2(v.x, v.x);
                    dup[2 * i + 1] = packf2(v.y, v.y);
                }
            }
            // F: out[cols] += rho[row] * W[row][cols]
#pragma unroll
            for (int cp = 0; cp < 4; cp++)
#pragma unroll
                for (int b = 0; b < 8; b++)
                    accF[cp * 8 + b] = ffma2(w8[cp], dup[b], accF[cp * 8 + b]);

            // T: out[row] += sum_cols W[row][cols] * rhoc[cols]  (rc in regs)
            ull accT[8];
#pragma unroll
            for (int b = 0; b < 8; b++) accT[b] = 0ull;
#pragma unroll
            for (int cp = 0; cp < 4; cp++)
#pragma unroll
                for (int b = 0; b < 8; b++)
                    accT[b] = ffma2(w8[cp], rc[cp * 8 + b], accT[b]);

            // 2-round shfl butterfly: 32 lanes -> 8 partial groups
            ull keep[4];
            {
                const int sel = lane & 1;
#pragma unroll
                for (int r = 0; r < 4; r++) {
                    ull snd = accT[sel ? r : r + 4];
                    ull rcv = __shfl_xor_sync(0xffffffffu, snd, 1);
                    keep[r] = add2(accT[sel ? r + 4 : r], rcv);
                }
            }
            ull keep2[2];
            {
                const int sel2 = (lane >> 1) & 1;
#pragma unroll
                for (int r = 0; r < 2; r++) {
                    ull snd = keep[sel2 ? r : r + 2];
                    ull rcv = __shfl_xor_sync(0xffffffffu, snd, 2);
                    keep2[r] = add2(keep[sel2 ? r + 2 : r], rcv);
                }
            }
            ulonglong2 st2; st2.x = keep2[0]; st2.y = keep2[1];
            *((ulonglong2*)(sT + (size_t)(row * 32 + lane) * 2)) = st2;
        }
        __syncthreads();

        // T reduction: 256 outputs (32 rows x 8 batches), 8 groups each
        {
            const ull* sTr = (const ull*)(smem + OFF_TS);
            const int r32 = t >> 3, b = t & 7;
            const int laneoff = 2 * ((b >> 1) & 1) + (b >> 2);
            float sum = 0.0f;
#pragma unroll
            for (int g = 0; g < 8; g++) {
                ull v = sTr[(size_t)(r32 * 32 + g * 4 + laneoff) * 2 + (b & 1)];
                float2 f = *reinterpret_cast<float2*>(&v);
                sum += f.x + f.y;
            }
            atomicAdd(&g_acc[b * D + row0 + s * SK + r32], sum);
        }
        stg ^= 1;
    }

    // F flush: stage accF, 8-way reduce over warps, atomic add
    __syncthreads();
    {
        ull* sF = (ull*)smem;                       // padded [cpb][257]
#pragma unroll
        for (int i = 0; i < 32; i++)
            sF[(size_t)i * 257 + w * 32 + jc] = accF[i];
    }
    __syncthreads();
    {
        const ull* sF = (const ull*)smem;
#pragma unroll
        for (int i = 0; i < 4; i++) {
            int idx = t * 4 + i;                    // 0..1023
            int jj  = idx >> 5;
            int cpb = idx & 31;
            float2 sum = make_float2(0.0f, 0.0f);
#pragma unroll
            for (int ww = 0; ww < 8; ww++) {
                ull v = sF[(size_t)cpb * 257 + ww * 32 + jj];
                float2 f = *reinterpret_cast<float2*>(&v);
                sum.x += f.x; sum.y += f.y;
            }
            int cp = cpb >> 3, b = cpb & 7;
            int col = col0 + jj * 8 + cp * 2;
            atomicAdd(&g_acc[b * D + col    ], sum.x);
            atomicAdd(&g_acc[b * D + col + 1], sum.y);
        }
    }
}

// ---------------------------------------------------------------------------
// Kernel 3: epilogue  out = (acc + bias + [Ux|0]) * rho'(s)
// ---------------------------------------------------------------------------
__global__ void epi_kernel(const float* __restrict__ Ux,
                           const float* __restrict__ s,
                           const float* __restrict__ bias,
                           float* __restrict__ out) {
    int idx = blockIdx.x * blockDim.x + threadIdx.x;
    if (idx >= BATCH * D) return;
    int b = idx >> 14;
    int j = idx & (D - 1);
    float r  = sigmoid4(s[idx]);
    float rd = 4.0f * r * (1.0f - r);
    float v  = g_acc[idx] + bias[j];
    if (j < H0) v += Ux[b * H0 + j];
    out[idx] = v * rd;
}

// ---------------------------------------------------------------------------
extern "C" void kernel_launch(void* const* d_in, const int* in_sizes, int n_in,
                              void* d_out, int out_size) {
    const float *Ux = nullptr, *s = nullptr, *W = nullptr, *bias = nullptr;
    for (int i = 0; i < n_in; i++) {
        switch (in_sizes[i]) {
            case 32768:     Ux   = (const float*)d_in[i]; break;
            case 131072:    s    = (const float*)d_in[i]; break;
            case 268435456: W    = (const float*)d_in[i]; break;
            case 16384:     bias = (const float*)d_in[i]; break;
            default: break;
        }
    }

    cudaFuncSetAttribute(mm_kernel, cudaFuncAttributeMaxDynamicSharedMemorySize,
                         SMEM_TOTAL);

    prep_kernel<<<512, 256>>>(s);
    mm_kernel<<<768, THREADS, SMEM_TOTAL>>>(W);
    epi_kernel<<<(BATCH * D + 255) / 256, 256>>>(Ux, s, bias, (float*)d_out);
}

// round 6
// speedup vs baseline: 1.0002x; 1.0002x over previous
#include <cuda_runtime.h>
#include <cstdint>

#define D      16384
#define BATCH  8
#define H0     4096

#define TK      256
#define TJ      256
#define SK      32
#define NSUB    8
#define THREADS 256

// smem layout (bytes)
#define OFF_W0  0
#define OFF_W1  32768
#define OFF_R0  65536
#define OFF_R1  66560
#define OFF_TS  67584
#define SMEM_TOTAL (OFF_TS + 16384)   // 83968 B
// F-flush overlays [0 .. 65792) after the main loop (W/rho stages dead then)

typedef unsigned long long ull;

__device__ float g_acc[BATCH * D];
__device__ ull   g_rho_bp[(size_t)D * 4];       // [k][bp]: (rho_{2bp}(k), rho_{2bp+1}(k))
__device__ ull   g_rhoc[(size_t)(D / 2) * 8];   // [j2][b]: (rho_b(2j2), rho_b(2j2+1))

__device__ __forceinline__ ull ffma2(ull a, ull b, ull c) {
    ull d;
    asm("fma.rn.f32x2 %0, %1, %2, %3;" : "=l"(d) : "l"(a), "l"(b), "l"(c));
    return d;
}
__device__ __forceinline__ ull add2(ull a, ull b) {
    ull d;
    asm("add.rn.f32x2 %0, %1, %2;" : "=l"(d) : "l"(a), "l"(b));
    return d;
}
__device__ __forceinline__ float sigmoid4(float x) {
    return 1.0f / (1.0f + expf(-4.0f * (x - 0.5f)));
}
__device__ __forceinline__ void cpa16(void* smem_dst, const void* gmem_src) {
    uint32_t sa = (uint32_t)__cvta_generic_to_shared(smem_dst);
    asm volatile("cp.async.cg.shared.global [%0], [%1], 16;\n" :: "r"(sa), "l"(gmem_src));
}
__device__ __forceinline__ ull packf2(float x, float y) {
    float2 v = make_float2(x, y);
    return *reinterpret_cast<ull*>(&v);
}

// ---------------------------------------------------------------------------
// Kernel 1: zero acc + build compact rho tables (coalesced writes)
// grid 512 x 256 = 131072 threads
// ---------------------------------------------------------------------------
__global__ void prep_kernel(const float* __restrict__ s) {
    int idx = blockIdx.x * blockDim.x + threadIdx.x;
    g_acc[idx] = 0.0f;
    if (idx < D * 4) {          // b-pair table for F
        int k = idx >> 2, i = idx & 3;
        g_rho_bp[idx] = packf2(sigmoid4(s[(2 * i) * D + k]),
                               sigmoid4(s[(2 * i + 1) * D + k]));
    }
    if (idx < (D / 2) * 8) {    // j-pair table for T
        int j2 = idx >> 3, b = idx & 7;
        g_rhoc[idx] = packf2(sigmoid4(s[b * D + 2 * j2]),
                             sigmoid4(s[b * D + 2 * j2 + 1]));
    }
}

// ---------------------------------------------------------------------------
// Kernel 2: symmetric block-tridiag matmul; each 256x256 upper-block tile is
// read from DRAM once and used in BOTH directions (F: rho_R @ B, T: rho_C @ B^T)
// in a single fused inner loop. rhoc lives in registers; rho b-pairs broadcast.
// ---------------------------------------------------------------------------
__global__ __launch_bounds__(THREADS, 1)
void mm_kernel(const float* __restrict__ W) {
    extern __shared__ char smem[];
    const int t    = threadIdx.x;
    const int lane = t & 31;
    const int w    = t >> 5;        // warp 0..7 = k-row group
    const int jc   = lane;          // col chunk (8 cols each)

    const int cta  = blockIdx.x;    // 0..767
    const int b3   = cta >> 8;
    const int rem  = cta & 255;
    const int it   = rem >> 4;
    const int jt   = rem & 15;
    const int row0 = b3 * 4096 + it * TK;
    const int col0 = (b3 + 1) * 4096 + jt * TJ;

    // rhoc for this thread's 8 fixed cols: 4 j-pairs x 8 batches, in registers
    ull rc[32];
    {
        const int j2b = (col0 >> 1) + jc * 4;
#pragma unroll
        for (int cp = 0; cp < 4; cp++)
#pragma unroll
            for (int b = 0; b < 8; b++)
                rc[cp * 8 + b] = g_rhoc[(size_t)(j2b + cp) * 8 + b];
    }

    auto load_sub = [&](int s, int stg) {
        char* dst = smem + (stg ? OFF_W1 : OFF_W0);
        const float* src = W + (size_t)(row0 + s * SK) * D + col0;
#pragma unroll
        for (int i = 0; i < 8; i++) {
            int idx = t + THREADS * i;          // 0..2047
            int r  = idx >> 6;
            int c4 = idx & 63;
            cpa16(dst + r * 1024 + c4 * 16, src + (size_t)r * D + c4 * 4);
        }
        if (t < 64) {
            char* rdst = smem + (stg ? OFF_R1 : OFF_R0);
            const char* rsrc = (const char*)g_rho_bp + (size_t)(row0 + s * SK) * 32;
            cpa16(rdst + t * 16, rsrc + t * 16);
        }
    };

    ull accF[32];
#pragma unroll
    for (int i = 0; i < 32; i++) accF[i] = 0ull;

    load_sub(0, 0);
    asm volatile("cp.async.commit_group;\n");

    int stg = 0;
    for (int s = 0; s < NSUB; s++) {
        if (s + 1 < NSUB) {
            load_sub(s + 1, stg ^ 1);
            asm volatile("cp.async.commit_group;\n");
            asm volatile("cp.async.wait_group 1;\n");
        } else {
            asm volatile("cp.async.wait_group 0;\n");
        }
        __syncthreads();

        const char* wbuf = smem + (stg ? OFF_W1 : OFF_W0);
        const char* rbuf = smem + (stg ? OFF_R1 : OFF_R0);
        ull* sT = (ull*)(smem + OFF_TS);

#pragma unroll
        for (int kq = 0; kq < 4; kq++) {
            const int row = w * 4 + kq;

            ull w8[4];
            {
                const ulonglong2* p = (const ulonglong2*)(wbuf + row * 1024 + jc * 32);
                ulonglong2 a = p[0], b_ = p[1];
                w8[0] = a.x; w8[1] = a.y; w8[2] = b_.x; w8[3] = b_.y;
            }
            ull dup[8];
            {
                const ulonglong2* p = (const ulonglong2*)(rbuf + row * 32);
                ulonglong2 a = p[0], b_ = p[1];
                ull bp[4] = {a.x, a.y, b_.x, b_.y};
#pragma unroll
                for (int i = 0; i < 4; i++) {
                    float2 v = *reinterpret_cast<float2*>(&bp[i]);
                    dup[2 * i]     = packf2(v.x, v.x);
                    dup[2 * i + 1] = packf2(v.y, v.y);
                }
            }
            // F: out[cols] += rho[row] * W[row][cols]
#pragma unroll
            for (int cp = 0; cp < 4; cp++)
#pragma unroll
                for (int b = 0; b < 8; b++)
                    accF[cp * 8 + b] = ffma2(w8[cp], dup[b], accF[cp * 8 + b]);

            // T: out[row] += sum_cols W[row][cols] * rhoc[cols]  (rc in regs)
            ull accT[8];
#pragma unroll
            for (int b = 0; b < 8; b++) accT[b] = 0ull;
#pragma unroll
            for (int cp = 0; cp < 4; cp++)
#pragma unroll
                for (int b = 0; b < 8; b++)
                    accT[b] = ffma2(w8[cp], rc[cp * 8 + b], accT[b]);

            // 2-round shfl butterfly: 32 lanes -> 8 partial groups
            ull keep[4];
            {
                const int sel = lane & 1;
#pragma unroll
                for (int r = 0; r < 4; r++) {
                    ull snd = accT[sel ? r : r + 4];
                    ull rcv = __shfl_xor_sync(0xffffffffu, snd, 1);
                    keep[r] = add2(accT[sel ? r + 4 : r], rcv);
                }
            }
            ull keep2[2];
            {
                const int sel2 = (lane >> 1) & 1;
#pragma unroll
                for (int r = 0; r < 2; r++) {
                    ull snd = keep[sel2 ? r : r + 2];
                    ull rcv = __shfl_xor_sync(0xffffffffu, snd, 2);
                    keep2[r] = add2(keep[sel2 ? r + 2 : r], rcv);
                }
            }
            ulonglong2 st2; st2.x = keep2[0]; st2.y = keep2[1];
            *((ulonglong2*)(sT + (size_t)(row * 32 + lane) * 2)) = st2;
        }
        __syncthreads();

        // T reduction: 256 outputs (32 rows x 8 batches), 8 groups each
        {
            const ull* sTr = (const ull*)(smem + OFF_TS);
            const int r32 = t >> 3, b = t & 7;
            const int laneoff = 2 * ((b >> 1) & 1) + (b >> 2);
            float sum = 0.0f;
#pragma unroll
            for (int g = 0; g < 8; g++) {
                ull v = sTr[(size_t)(r32 * 32 + g * 4 + laneoff) * 2 + (b & 1)];
                float2 f = *reinterpret_cast<float2*>(&v);
                sum += f.x + f.y;
            }
            atomicAdd(&g_acc[b * D + row0 + s * SK + r32], sum);
        }
        stg ^= 1;
    }

    // F flush: stage accF, 8-way reduce over warps, atomic add
    __syncthreads();
    {
        ull* sF = (ull*)smem;                       // padded [cpb][257]
#pragma unroll
        for (int i = 0; i < 32; i++)
            sF[(size_t)i * 257 + w * 32 + jc] = accF[i];
    }
    __syncthreads();
    {
        const ull* sF = (const ull*)smem;
#pragma unroll
        for (int i = 0; i < 4; i++) {
            int idx = t * 4 + i;                    // 0..1023
            int jj  = idx >> 5;
            int cpb = idx & 31;
            float2 sum = make_float2(0.0f, 0.0f);
#pragma unroll
            for (int ww = 0; ww < 8; ww++) {
                ull v = sF[(size_t)cpb * 257 + ww * 32 + jj];
                float2 f = *reinterpret_cast<float2*>(&v);
                sum.x += f.x; sum.y += f.y;
            }
            int cp = cpb >> 3, b = cpb & 7;
            int col = col0 + jj * 8 + cp * 2;
            atomicAdd(&g_acc[b * D + col    ], sum.x);
            atomicAdd(&g_acc[b * D + col + 1], sum.y);
        }
    }
}

// ---------------------------------------------------------------------------
// Kernel 3: epilogue  out = (acc + bias + [Ux|0]) * rho'(s)
// ---------------------------------------------------------------------------
__global__ void epi_kernel(const float* __restrict__ Ux,
                           const float* __restrict__ s,
                           const float* __restrict__ bias,
                           float* __restrict__ out) {
    int idx = blockIdx.x * blockDim.x + threadIdx.x;
    if (idx >= BATCH * D) return;
    int b = idx >> 14;
    int j = idx & (D - 1);
    float r  = sigmoid4(s[idx]);
    float rd = 4.0f * r * (1.0f - r);
    float v  = g_acc[idx] + bias[j];
    if (j < H0) v += Ux[b * H0 + j];
    out[idx] = v * rd;
}

// ---------------------------------------------------------------------------
extern "C" void kernel_launch(void* const* d_in, const int* in_sizes, int n_in,
                              void* d_out, int out_size) {
    const float *Ux = nullptr, *s = nullptr, *W = nullptr, *bias = nullptr;
    for (int i = 0; i < n_in; i++) {
        switch (in_sizes[i]) {
            case 32768:     Ux   = (const float*)d_in[i]; break;
            case 131072:    s    = (const float*)d_in[i]; break;
            case 268435456: W    = (const float*)d_in[i]; break;
            case 16384:     bias = (const float*)d_in[i]; break;
            default: break;
        }
    }

    cudaFuncSetAttribute(mm_kernel, cudaFuncAttributeMaxDynamicSharedMemorySize,
                         SMEM_TOTAL);

    prep_kernel<<<512, 256>>>(s);
    mm_kernel<<<768, THREADS, SMEM_TOTAL>>>(W);
    epi_kernel<<<(BATCH * D + 255) / 256, 256>>>(Ux, s, bias, (float*)d_out);
}

// round 7
// speedup vs baseline: 1.0045x; 1.0043x over previous
#include <cuda_runtime.h>
#include <cstdint>

#define D      16384
#define BATCH  8
#define H0     4096

#define TK      256
#define TJ      256
#define SK      32
#define NSUB    8
#define THREADS 256

// smem layout (bytes)
#define OFF_W0  0
#define OFF_W1  32768
#define OFF_R0  65536
#define OFF_R1  66560
#define OFF_TS  67584
#define SMEM_TOTAL (OFF_TS + 16384)   // 83968 B
// F-flush overlays [0 .. 65792) after the main loop (W/rho stages dead then)

typedef unsigned long long ull;

__device__ float g_acc[BATCH * D];
__device__ ull   g_rho_bp[(size_t)D * 4];       // [k][bp]: (rho_{2bp}(k), rho_{2bp+1}(k))
__device__ ull   g_rhoc[(size_t)(D / 2) * 8];   // [j2][b]: (rho_b(2j2), rho_b(2j2+1))

__device__ __forceinline__ ull ffma2(ull a, ull b, ull c) {
    ull d;
    asm("fma.rn.f32x2 %0, %1, %2, %3;" : "=l"(d) : "l"(a), "l"(b), "l"(c));
    return d;
}
__device__ __forceinline__ ull add2(ull a, ull b) {
    ull d;
    asm("add.rn.f32x2 %0, %1, %2;" : "=l"(d) : "l"(a), "l"(b));
    return d;
}
__device__ __forceinline__ float sigmoid4(float x) {
    return 1.0f / (1.0f + expf(-4.0f * (x - 0.5f)));
}
__device__ __forceinline__ void cpa16(void* smem_dst, const void* gmem_src) {
    uint32_t sa = (uint32_t)__cvta_generic_to_shared(smem_dst);
    asm volatile("cp.async.cg.shared.global [%0], [%1], 16;\n" :: "r"(sa), "l"(gmem_src));
}
__device__ __forceinline__ ull packf2(float x, float y) {
    float2 v = make_float2(x, y);
    return *reinterpret_cast<ull*>(&v);
}

// ---------------------------------------------------------------------------
// Kernel 1: zero acc + build compact rho tables (coalesced writes)
// grid 512 x 256 = 131072 threads
// ---------------------------------------------------------------------------
__global__ void prep_kernel(const float* __restrict__ s) {
    int idx = blockIdx.x * blockDim.x + threadIdx.x;
    g_acc[idx] = 0.0f;
    if (idx < D * 4) {          // b-pair table for F
        int k = idx >> 2, i = idx & 3;
        g_rho_bp[idx] = packf2(sigmoid4(s[(2 * i) * D + k]),
                               sigmoid4(s[(2 * i + 1) * D + k]));
    }
    if (idx < (D / 2) * 8) {    // j-pair table for T
        int j2 = idx >> 3, b = idx & 7;
        g_rhoc[idx] = packf2(sigmoid4(s[b * D + 2 * j2]),
                             sigmoid4(s[b * D + 2 * j2 + 1]));
    }
}

// ---------------------------------------------------------------------------
// Kernel 2: symmetric block-tridiag matmul; each 256x256 upper-block tile is
// read from DRAM once and used in BOTH directions (F: rho_R @ B, T: rho_C @ B^T)
// in a single fused inner loop. rhoc lives in registers; rho b-pairs broadcast.
// ---------------------------------------------------------------------------
__global__ __launch_bounds__(THREADS, 1)
void mm_kernel(const float* __restrict__ W) {
    extern __shared__ char smem[];
    const int t    = threadIdx.x;
    const int lane = t & 31;
    const int w    = t >> 5;        // warp 0..7 = k-row group
    const int jc   = lane;          // col chunk (8 cols each)

    const int cta  = blockIdx.x;    // 0..767
    const int b3   = cta >> 8;
    const int rem  = cta & 255;
    const int it   = rem >> 4;
    const int jt   = rem & 15;
    const int row0 = b3 * 4096 + it * TK;
    const int col0 = (b3 + 1) * 4096 + jt * TJ;

    // rhoc for this thread's 8 fixed cols: 4 j-pairs x 8 batches, in registers
    ull rc[32];
    {
        const int j2b = (col0 >> 1) + jc * 4;
#pragma unroll
        for (int cp = 0; cp < 4; cp++)
#pragma unroll
            for (int b = 0; b < 8; b++)
                rc[cp * 8 + b] = g_rhoc[(size_t)(j2b + cp) * 8 + b];
    }

    auto load_sub = [&](int s, int stg) {
        char* dst = smem + (stg ? OFF_W1 : OFF_W0);
        const float* src = W + (size_t)(row0 + s * SK) * D + col0;
#pragma unroll
        for (int i = 0; i < 8; i++) {
            int idx = t + THREADS * i;          // 0..2047
            int r  = idx >> 6;
            int c4 = idx & 63;
            cpa16(dst + r * 1024 + c4 * 16, src + (size_t)r * D + c4 * 4);
        }
        if (t < 64) {
            char* rdst = smem + (stg ? OFF_R1 : OFF_R0);
            const char* rsrc = (const char*)g_rho_bp + (size_t)(row0 + s * SK) * 32;
            cpa16(rdst + t * 16, rsrc + t * 16);
        }
    };

    ull accF[32];
#pragma unroll
    for (int i = 0; i < 32; i++) accF[i] = 0ull;

    load_sub(0, 0);
    asm volatile("cp.async.commit_group;\n");

    int stg = 0;
    for (int s = 0; s < NSUB; s++) {
        if (s + 1 < NSUB) {
            load_sub(s + 1, stg ^ 1);
            asm volatile("cp.async.commit_group;\n");
            asm volatile("cp.async.wait_group 1;\n");
        } else {
            asm volatile("cp.async.wait_group 0;\n");
        }
        __syncthreads();

        const char* wbuf = smem + (stg ? OFF_W1 : OFF_W0);
        const char* rbuf = smem + (stg ? OFF_R1 : OFF_R0);
        ull* sT = (ull*)(smem + OFF_TS);

#pragma unroll
        for (int kq = 0; kq < 4; kq++) {
            const int row = w * 4 + kq;

            ull w8[4];
            {
                const ulonglong2* p = (const ulonglong2*)(wbuf + row * 1024 + jc * 32);
                ulonglong2 a = p[0], b_ = p[1];
                w8[0] = a.x; w8[1] = a.y; w8[2] = b_.x; w8[3] = b_.y;
            }
            ull dup[8];
            {
                const ulonglong2* p = (const ulonglong2*)(rbuf + row * 32);
                ulonglong2 a = p[0], b_ = p[1];
                ull bp[4] = {a.x, a.y, b_.x, b_.y};
#pragma unroll
                for (int i = 0; i < 4; i++) {
                    float2 v = *reinterpret_cast<float2*>(&bp[i]);
                    dup[2 * i]     = packf2(v.x, v.x);
                    dup[2 * i + 1] = packf2(v.y, v.y);
                }
            }
            // F: out[cols] += rho[row] * W[row][cols]
#pragma unroll
            for (int cp = 0; cp < 4; cp++)
#pragma unroll
                for (int b = 0; b < 8; b++)
                    accF[cp * 8 + b] = ffma2(w8[cp], dup[b], accF[cp * 8 + b]);

            // T: out[row] += sum_cols W[row][cols] * rhoc[cols]  (rc in regs)
            ull accT[8];
#pragma unroll
            for (int b = 0; b < 8; b++) accT[b] = 0ull;
#pragma unroll
            for (int cp = 0; cp < 4; cp++)
#pragma unroll
                for (int b = 0; b < 8; b++)
                    accT[b] = ffma2(w8[cp], rc[cp * 8 + b], accT[b]);

            // 2-round shfl butterfly: 32 lanes -> 8 partial groups
            ull keep[4];
            {
                const int sel = lane & 1;
#pragma unroll
                for (int r = 0; r < 4; r++) {
                    ull snd = accT[sel ? r : r + 4];
                    ull rcv = __shfl_xor_sync(0xffffffffu, snd, 1);
                    keep[r] = add2(accT[sel ? r + 4 : r], rcv);
                }
            }
            ull keep2[2];
            {
                const int sel2 = (lane >> 1) & 1;
#pragma unroll
                for (int r = 0; r < 2; r++) {
                    ull snd = keep[sel2 ? r : r + 2];
                    ull rcv = __shfl_xor_sync(0xffffffffu, snd, 2);
                    keep2[r] = add2(keep[sel2 ? r + 2 : r], rcv);
                }
            }
            ulonglong2 st2; st2.x = keep2[0]; st2.y = keep2[1];
            *((ulonglong2*)(sT + (size_t)(row * 32 + lane) * 2)) = st2;
        }
        __syncthreads();

        // T reduction: 256 outputs (32 rows x 8 batches), 8 groups each
        {
            const ull* sTr = (const ull*)(smem + OFF_TS);
            const int r32 = t >> 3, b = t & 7;
            const int laneoff = 2 * ((b >> 1) & 1) + (b >> 2);
            float sum = 0.0f;
#pragma unroll
            for (int g = 0; g < 8; g++) {
                ull v = sTr[(size_t)(r32 * 32 + g * 4 + laneoff) * 2 + (b & 1)];
                float2 f = *reinterpret_cast<float2*>(&v);
                sum += f.x + f.y;
            }
            atomicAdd(&g_acc[b * D + row0 + s * SK + r32], sum);
        }
        stg ^= 1;
    }

    // F flush: stage accF, 8-way reduce over warps, atomic add
    __syncthreads();
    {
        ull* sF = (ull*)smem;                       // padded [cpb][257]
#pragma unroll
        for (int i = 0; i < 32; i++)
            sF[(size_t)i * 257 + w * 32 + jc] = accF[i];
    }
    __syncthreads();
    {
        const ull* sF = (const ull*)smem;
#pragma unroll
        for (int i = 0; i < 4; i++) {
            int idx = t * 4 + i;                    // 0..1023
            int jj  = idx >> 5;
            int cpb = idx & 31;
            float2 sum = make_float2(0.0f, 0.0f);
#pragma unroll
            for (int ww = 0; ww < 8; ww++) {
                ull v = sF[(size_t)cpb * 257 + ww * 32 + jj];
                float2 f = *reinterpret_cast<float2*>(&v);
                sum.x += f.x; sum.y += f.y;
            }
            int cp = cpb >> 3, b = cpb & 7;
            int col = col0 + jj * 8 + cp * 2;
            atomicAdd(&g_acc[b * D + col    ], sum.x);
            atomicAdd(&g_acc[b * D + col + 1], sum.y);
        }
    }
}

// ---------------------------------------------------------------------------
// Kernel 3: epilogue  out = (acc + bias + [Ux|0]) * rho'(s)
// ---------------------------------------------------------------------------
__global__ void epi_kernel(const float* __restrict__ Ux,
                           const float* __restrict__ s,
                           const float* __restrict__ bias,
                           float* __restrict__ out) {
    int idx = blockIdx.x * blockDim.x + threadIdx.x;
    if (idx >= BATCH * D) return;
    int b = idx >> 14;
    int j = idx & (D - 1);
    float r  = sigmoid4(s[idx]);
    float rd = 4.0f * r * (1.0f - r);
    float v  = g_acc[idx] + bias[j];
    if (j < H0) v += Ux[b * H0 + j];
    out[idx] = v * rd;
}

// ---------------------------------------------------------------------------
extern "C" void kernel_launch(void* const* d_in, const int* in_sizes, int n_in,
                              void* d_out, int out_size) {
    const float *Ux = nullptr, *s = nullptr, *W = nullptr, *bias = nullptr;
    for (int i = 0; i < n_in; i++) {
        switch (in_sizes[i]) {
            case 32768:     Ux   = (const float*)d_in[i]; break;
            case 131072:    s    = (const float*)d_in[i]; break;
            case 268435456: W    = (const float*)d_in[i]; break;
            case 16384:     bias = (const float*)d_in[i]; break;
            default: break;
        }
    }

    cudaFuncSetAttribute(mm_kernel, cudaFuncAttributeMaxDynamicSharedMemorySize,
                         SMEM_TOTAL);

    prep_kernel<<<512, 256>>>(s);
    mm_kernel<<<768, THREADS, SMEM_TOTAL>>>(W);
    epi_kernel<<<(BATCH * D + 255) / 256, 256>>>(Ux, s, bias, (float*)d_out);
}